// round 5
// baseline (speedup 1.0000x reference)
#include <cuda_runtime.h>
#include <cstdint>
#include <cstddef>

#define Tn 1024
#define Bn 512
#define Hn 128
#define In 64
#define G3 384

// 805 MB scratch for precomputed input-side gate projections: xg[b][t][g]
__device__ float g_xg[(size_t)Bn * Tn * G3];

// ---------------------------------------------------------------------------
// Packed f32x2 FMA (Blackwell): d.lo += a.lo*b.lo ; d.hi += a.hi*b.hi
// ---------------------------------------------------------------------------
__device__ __forceinline__ void ffma2(unsigned long long& d,
                                      const unsigned long long a,
                                      const unsigned long long b) {
    asm("fma.rn.f32x2 %0, %1, %2, %0;" : "+l"(d) : "l"(a), "l"(b));
}

__device__ __forceinline__ float hsum2(unsigned long long v) {
    float lo, hi;
    asm("mov.b64 {%0, %1}, %2;" : "=f"(lo), "=f"(hi) : "l"(v));
    return lo + hi;
}

__device__ __forceinline__ float sigf(float x) {
    return __fdividef(1.0f, 1.0f + __expf(-x));
}
__device__ __forceinline__ float tanh_fast(float x) {
    return 1.0f - __fdividef(2.0f, 1.0f + __expf(2.0f * x));
}

// ---------------------------------------------------------------------------
// Kernel 1: xg[r][g] = x[r][:] . W_ih[g][:] + b_ih[g] + (g<256 ? b_hh[g] : 0)
// 64-row x 96-col tiles (was 128-row): acc 48 regs, smem 42.5 KB static ->
// 2 blocks/SM for latency hiding. Thread tile 4 rows x 6 cols.
// ---------------------------------------------------------------------------
__global__ void __launch_bounds__(256, 2)
xg_gemm(const float* __restrict__ x,
        const float* __restrict__ Wih,
        const float* __restrict__ bih,
        const float* __restrict__ bhh) {
    __shared__ __align__(16) float xs[64 * 64];   // [row][k]
    __shared__ __align__(16) float ws[96 * 68];   // [col][k] padded

    const int tid = threadIdx.x;
    const int r0 = blockIdx.x * 64;
    const int cb = blockIdx.y;       // 0..3 -> 96 gate-cols each

    {
        const float4* xg4 = (const float4*)(x + (size_t)r0 * 64);
        float4* xs4 = (float4*)xs;
        #pragma unroll
        for (int i = tid; i < 64 * 16; i += 256) xs4[i] = xg4[i];
    }
    {
        const float4* wg4 = (const float4*)(Wih + (size_t)cb * 96 * 64);
        #pragma unroll
        for (int i = tid; i < 96 * 16; i += 256) {
            int g = i >> 4, k4 = i & 15;
            *(float4*)(ws + g * 68 + k4 * 4) = wg4[i];
        }
    }
    __syncthreads();

    const int ry = tid >> 4;   // 0..15 -> rows ry*4 .. +4
    const int cx = tid & 15;   // cols cx + 16*jj

    unsigned long long acc[4][6];
    #pragma unroll
    for (int i = 0; i < 4; i++)
        #pragma unroll
        for (int jj = 0; jj < 6; jj++) acc[i][jj] = 0ULL;

    #pragma unroll
    for (int k4 = 0; k4 < 16; k4++) {
        ulonglong2 wv[6];
        #pragma unroll
        for (int jj = 0; jj < 6; jj++)
            wv[jj] = *(const ulonglong2*)(ws + (cx + 16 * jj) * 68 + k4 * 4);
        #pragma unroll
        for (int i = 0; i < 4; i++) {
            ulonglong2 xv = *(const ulonglong2*)(xs + (ry * 4 + i) * 64 + k4 * 4);
            #pragma unroll
            for (int jj = 0; jj < 6; jj++) {
                ffma2(acc[i][jj], xv.x, wv[jj].x);
                ffma2(acc[i][jj], xv.y, wv[jj].y);
            }
        }
    }

    #pragma unroll
    for (int jj = 0; jj < 6; jj++) {
        const int g = cb * 96 + cx + 16 * jj;
        const float bias = bih[g] + (g < 256 ? bhh[g] : 0.0f);
        #pragma unroll
        for (int i = 0; i < 4; i++) {
            const int r = r0 + ry * 4 + i;
            g_xg[(size_t)r * G3 + g] = hsum2(acc[i][jj]) + bias;
        }
    }
}

// ---------------------------------------------------------------------------
// Kernel 2: GRU recurrence + final FC.
// 128 blocks x 4 batches, 512 threads. Thread: j = tid>>2 (hidden unit),
// q = tid&3 (k-quarter of 32). r,z gate W quarters in regs (64 regs);
// n gate W from smem [128][132]. h double-buffered, rows padded to 148
// (reads conflict-free broadcast; writes bank-distinct). One barrier/step.
// Reduce-scatter over quarters: shfl_xor 2 then 1; thread keeps batch b=q.
// ---------------------------------------------------------------------------
#define HROW 148   // per-batch padded h row; quarter q at offset q*36
__device__ __forceinline__ int hpos(int k) { return (k >> 5) * 36 + (k & 31); }

#define GRU_SMEM_FLOATS (128 * 132 + 2 * 4 * HROW)
#define GRU_SMEM_BYTES  (GRU_SMEM_FLOATS * 4)

__global__ void __launch_bounds__(512, 1)
gru_kernel(const float* __restrict__ Whh,
           const float* __restrict__ bhh,
           const float* __restrict__ Wfc,
           const float* __restrict__ bfc,
           float* __restrict__ out) {
    extern __shared__ __align__(16) float sm[];
    float* Wn_s = sm;                   // [128][132] n-gate rows, padded
    float* hs = sm + 128 * 132;         // [2][4][HROW]

    const int tid = threadIdx.x;
    const int j = tid >> 2;      // 0..127
    const int q = tid & 3;       // k-quarter
    const int b0 = blockIdx.x * 4;

    // n-gate W -> smem (coalesced float4)
    #pragma unroll
    for (int i = tid; i < 128 * 32; i += 512) {
        int g = i >> 5, k4 = i & 31;
        *(float4*)(Wn_s + g * 132 + k4 * 4) = ((const float4*)(Whh + 256 * 128))[i];
    }
    // Zero read-buffer 0
    for (int i = tid; i < 4 * HROW; i += 512) hs[i] = 0.0f;

    // r,z gate quarters -> registers (2 x 8 ull2 = 64 regs)
    ulonglong2 wrr[8], wzr[8];
    {
        const ulonglong2* wr_g = (const ulonglong2*)(Whh + (size_t)j * 128 + q * 32);
        const ulonglong2* wz_g = (const ulonglong2*)(Whh + (size_t)(j + 128) * 128 + q * 32);
        #pragma unroll
        for (int kk = 0; kk < 8; kk++) { wrr[kk] = wr_g[kk]; wzr[kk] = wz_g[kk]; }
    }
    const float bn = bhh[256 + j];     // n-gate hidden bias (inside r*(...))
    float hold = 0.0f;                 // own h[j] for batch b0+q

    const float* xp = g_xg + ((size_t)(b0 + q) * Tn) * G3 + j;
    const ulonglong2* WnL = (const ulonglong2*)(Wn_s + j * 132 + q * 32);

    __syncthreads();

    for (int t = 0; t < Tn; t++) {
        const float* hrd = hs + (t & 1) * (4 * HROW);
        float* hwr = hs + ((t & 1) ^ 1) * (4 * HROW);

        // Prefetch this thread's batch input projections (hidden under dot)
        const float xr = xp[0], xz = xp[128], xn = xp[256];
        xp += G3;

        unsigned long long acc[3][4];
        #pragma unroll
        for (int g = 0; g < 3; g++)
            #pragma unroll
            for (int b = 0; b < 4; b++) acc[g][b] = 0ULL;

        const float* hbase = hrd + q * 36;
        #pragma unroll
        for (int kk = 0; kk < 8; kk++) {
            const ulonglong2 wr = wrr[kk];
            const ulonglong2 wz = wzr[kk];
            const ulonglong2 wn = WnL[kk];
            #pragma unroll
            for (int b = 0; b < 4; b++) {
                ulonglong2 hv = *(const ulonglong2*)(hbase + b * HROW + kk * 4);
                ffma2(acc[0][b], wr.x, hv.x); ffma2(acc[0][b], wr.y, hv.y);
                ffma2(acc[1][b], wz.x, hv.x); ffma2(acc[1][b], wz.y, hv.y);
                ffma2(acc[2][b], wn.x, hv.x); ffma2(acc[2][b], wn.y, hv.y);
            }
        }

        // Horizontal sums (12 per thread)
        float s[3][4];
        #pragma unroll
        for (int g = 0; g < 3; g++)
            #pragma unroll
            for (int b = 0; b < 4; b++) s[g][b] = hsum2(acc[g][b]);

        // Reduce-scatter over the 4 k-quarters (lanes 4j+q; xor 2 then 1).
        // Scalar ternary selects only — no dynamic array indexing.
        const bool hi = (q & 2) != 0;
        const bool lo = (q & 1) != 0;
        float tot[3];
        #pragma unroll
        for (int g = 0; g < 3; g++) {
            float k0 = hi ? s[g][2] : s[g][0];
            float k1 = hi ? s[g][3] : s[g][1];
            float s0 = hi ? s[g][0] : s[g][2];
            float s1 = hi ? s[g][1] : s[g][3];
            float p0 = k0 + __shfl_xor_sync(0xFFFFFFFFu, s0, 2);
            float p1 = k1 + __shfl_xor_sync(0xFFFFFFFFu, s1, 2);
            float kp = lo ? p1 : p0;
            float sp = lo ? p0 : p1;
            tot[g] = kp + __shfl_xor_sync(0xFFFFFFFFu, sp, 1);
        }

        // Gates for (j, b = q)
        {
            float r = sigf(xr + tot[0]);
            float z = sigf(xz + tot[1]);
            float n = tanh_fast(fmaf(r, tot[2] + bn, xn));
            float hnew = fmaf(z, hold - n, n);   // (1-z)*n + z*h
            hold = hnew;
            hwr[q * HROW + hpos(j)] = hnew;
        }

        __syncthreads();
    }

    // Final h is in buffer 0 (t=1023 writes buf (1023+1)&1 = 0).
    // FC: out[b][o] = h_T[b] . W_fc[o] + b_fc[o]
    if (tid < 4 * 51) {
        const int b = tid / 51, o = tid % 51;
        float a = bfc[o];
        const float* wf = Wfc + o * 128;
        const float* hp = hs + b * HROW;
        #pragma unroll 8
        for (int k = 0; k < 128; k++) a = fmaf(hp[hpos(k)], wf[k], a);
        out[(b0 + b) * 51 + o] = a;
    }
}

// ---------------------------------------------------------------------------
// Launch
// ---------------------------------------------------------------------------
extern "C" void kernel_launch(void* const* d_in, const int* in_sizes, int n_in,
                              void* d_out, int out_size) {
    const float* x    = (const float*)d_in[0];  // [512,1,1024,64]
    const float* Wih  = (const float*)d_in[1];  // [384,64]
    const float* Whh  = (const float*)d_in[2];  // [384,128]
    const float* bih  = (const float*)d_in[3];  // [384]
    const float* bhh  = (const float*)d_in[4];  // [384]
    const float* Wfc  = (const float*)d_in[5];  // [51,128]
    const float* bfc  = (const float*)d_in[6];  // [51]
    float* out = (float*)d_out;                 // [512,51]

    static int attr_done = 0;
    if (!attr_done) {
        cudaFuncSetAttribute(gru_kernel,
                             cudaFuncAttributeMaxDynamicSharedMemorySize,
                             GRU_SMEM_BYTES);
        attr_done = 1;
    }

    xg_gemm<<<dim3((Bn * Tn) / 64, 4, 1), 256>>>(x, Wih, bih, bhh);
    gru_kernel<<<128, 512, GRU_SMEM_BYTES>>>(Whh, bhh, Wfc, bfc, out);
}

// round 8
// speedup vs baseline: 1.0324x; 1.0324x over previous
#include <cuda_runtime.h>
#include <mma.h>
#include <cstdint>
#include <cstddef>

using namespace nvcuda;

#define Tn 1024
#define Bn 512
#define Hn 128
#define In 64
#define G3 384

// 805 MB scratch for precomputed input-side gate projections: xg[b][t][g]
__device__ float g_xg[(size_t)Bn * Tn * G3];
// tf32-split input weights (hi + lo), each [384][64]
__device__ float g_whi[G3 * In];
__device__ float g_wlo[G3 * In];

// ---------------------------------------------------------------------------
// Common helpers
// ---------------------------------------------------------------------------
__device__ __forceinline__ void ffma2(unsigned long long& d,
                                      const unsigned long long a,
                                      const unsigned long long b) {
    asm("fma.rn.f32x2 %0, %1, %2, %0;" : "+l"(d) : "l"(a), "l"(b));
}

__device__ __forceinline__ float hsum2(unsigned long long v) {
    float lo, hi;
    asm("mov.b64 {%0, %1}, %2;" : "=f"(lo), "=f"(hi) : "l"(v));
    return lo + hi;
}

__device__ __forceinline__ float sigf(float x) {
    return __fdividef(1.0f, 1.0f + __expf(-x));
}
__device__ __forceinline__ float tanh_fast(float x) {
    return 1.0f - __fdividef(2.0f, 1.0f + __expf(2.0f * x));
}

// ---------------------------------------------------------------------------
// Kernel 0: split W_ih into tf32 hi/lo parts (runs once per launch, cheap)
// ---------------------------------------------------------------------------
__global__ void wsplit(const float* __restrict__ Wih) {
    int i = blockIdx.x * 256 + threadIdx.x;
    if (i < G3 * In) {
        float v = Wih[i];
        float h = wmma::__float_to_tf32(v);
        g_whi[i] = h;
        g_wlo[i] = wmma::__float_to_tf32(v - h);
    }
}

// ---------------------------------------------------------------------------
// Kernel 1 (tensor-core, wmma tf32 3-term split):
// xg[r][g] = x[r][:] . W_ih[g][:] + b_ih[g] + (g<256 ? b_hh[g] : 0)
// Block: 128 rows (8 warps x 16), all 384 gate cols. Warp: 16 rows,
// 24 col-tiles of 16, K=64 as 8 k-steps. A frags cached in regs (hi/lo),
// B frags from pre-split global (L1/L2-hot). Accumulator initialized from
// a replicated-bias smem tile; direct store to g_xg.
// ---------------------------------------------------------------------------
typedef wmma::fragment<wmma::matrix_a, 16, 16, 8, wmma::precision::tf32,
                       wmma::row_major> FragA;
typedef wmma::fragment<wmma::matrix_b, 16, 16, 8, wmma::precision::tf32,
                       wmma::col_major> FragB;
typedef wmma::fragment<wmma::accumulator, 16, 16, 8, float> FragC;

__global__ void __launch_bounds__(256)
xg_gemm_tc(const float* __restrict__ x,
           const float* __restrict__ bih,
           const float* __restrict__ bhh) {
    __shared__ __align__(16) float bias_t[16 * 384];   // 24 KB, 16 identical rows

    const int tid = threadIdx.x;
    const int wid = tid >> 5;

    // Build replicated bias tile
    for (int i = tid; i < 16 * 384; i += 256) {
        int g = i % 384;
        bias_t[i] = bih[g] + (g < 256 ? bhh[g] : 0.0f);
    }
    __syncthreads();

    const int row0 = blockIdx.x * 128 + wid * 16;

    // Load + split-convert A fragments for all 8 k-steps (cached in regs)
    FragA a_hi[8], a_lo[8];
    #pragma unroll
    for (int k = 0; k < 8; k++) {
        FragA ar;
        wmma::load_matrix_sync(ar, x + (size_t)row0 * 64 + k * 8, 64);
        #pragma unroll
        for (int e = 0; e < ar.num_elements; e++) {
            float v = ar.x[e];
            float h = wmma::__float_to_tf32(v);
            a_hi[k].x[e] = h;
            a_lo[k].x[e] = wmma::__float_to_tf32(v - h);
        }
    }

    // 24 column tiles of 16 gates
    for (int ct = 0; ct < 24; ct++) {
        FragC c;
        wmma::load_matrix_sync(c, bias_t + ct * 16, 384, wmma::mem_row_major);

        #pragma unroll
        for (int k = 0; k < 8; k++) {
            FragB b_hi, b_lo;
            const float* bp = g_whi + (size_t)ct * 16 * 64 + k * 8;
            const float* bq = g_wlo + (size_t)ct * 16 * 64 + k * 8;
            wmma::load_matrix_sync(b_hi, bp, 64);
            wmma::load_matrix_sync(b_lo, bq, 64);
            wmma::mma_sync(c, a_hi[k], b_hi, c);
            wmma::mma_sync(c, a_lo[k], b_hi, c);
            wmma::mma_sync(c, a_hi[k], b_lo, c);
        }

        wmma::store_matrix_sync(g_xg + (size_t)row0 * 384 + ct * 16, c, 384,
                                wmma::mem_row_major);
    }
}

// ---------------------------------------------------------------------------
// Kernel 2: GRU recurrence + final FC. (R4 config — proven 1732 us.)
// 128 blocks x 4 batches, 256 threads. Thread: j = tid>>1, half = tid&1.
// All 3 gate W row-halves in registers; h double-buffered; 1 barrier/step;
// cross-half reduction via shfl_xor(.,1).
// ---------------------------------------------------------------------------
#define HROW 136
__device__ __forceinline__ int hpos(int k) { return k + ((k >> 6) << 2); }

__global__ void __launch_bounds__(256, 1)
gru_kernel(const float* __restrict__ Whh,
           const float* __restrict__ bhh,
           const float* __restrict__ Wfc,
           const float* __restrict__ bfc,
           float* __restrict__ out) {
    __shared__ __align__(16) float hs[2 * 4 * HROW];

    const int tid = threadIdx.x;
    const int j = tid >> 1;
    const int half = tid & 1;
    const int b0 = blockIdx.x * 4;

    for (int i = tid; i < 4 * HROW; i += 256) hs[i] = 0.0f;

    ulonglong2 wrr[16], wzr[16], wnr[16];
    {
        const ulonglong2* wr_g = (const ulonglong2*)(Whh + (size_t)j * 128 + half * 64);
        const ulonglong2* wz_g = (const ulonglong2*)(Whh + (size_t)(j + 128) * 128 + half * 64);
        const ulonglong2* wn_g = (const ulonglong2*)(Whh + (size_t)(j + 256) * 128 + half * 64);
        #pragma unroll
        for (int kk = 0; kk < 16; kk++) {
            wrr[kk] = wr_g[kk];
            wzr[kk] = wz_g[kk];
            wnr[kk] = wn_g[kk];
        }
    }
    const float bn = bhh[256 + j];
    float hold[2] = {0.f, 0.f};

    const size_t xgA = ((size_t)(b0 + 2 * half) * Tn) * G3 + j;
    const size_t xgB = ((size_t)(b0 + 2 * half + 1) * Tn) * G3 + j;

    __syncthreads();

    for (int t = 0; t < Tn; t++) {
        const float* hrd = hs + (t & 1) * (4 * HROW);
        float* hwr = hs + ((t & 1) ^ 1) * (4 * HROW);

        const float* xpA = g_xg + xgA + (size_t)t * G3;
        const float* xpB = g_xg + xgB + (size_t)t * G3;
        float xr0 = xpA[0], xz0 = xpA[128], xn0 = xpA[256];
        float xr1 = xpB[0], xz1 = xpB[128], xn1 = xpB[256];

        unsigned long long acc[3][4];
        #pragma unroll
        for (int g = 0; g < 3; g++)
            #pragma unroll
            for (int b = 0; b < 4; b++) acc[g][b] = 0ULL;

        const float* hbase = hrd + half * 68;
        #pragma unroll
        for (int kk = 0; kk < 16; kk++) {
            const ulonglong2 wr = wrr[kk], wz = wzr[kk], wn = wnr[kk];
            #pragma unroll
            for (int b = 0; b < 4; b++) {
                ulonglong2 hv = *(const ulonglong2*)(hbase + b * HROW + kk * 4);
                ffma2(acc[0][b], wr.x, hv.x); ffma2(acc[0][b], wr.y, hv.y);
                ffma2(acc[1][b], wz.x, hv.x); ffma2(acc[1][b], wz.y, hv.y);
                ffma2(acc[2][b], wn.x, hv.x); ffma2(acc[2][b], wn.y, hv.y);
            }
        }

        float s[3][4];
        #pragma unroll
        for (int g = 0; g < 3; g++)
            #pragma unroll
            for (int b = 0; b < 4; b++) s[g][b] = hsum2(acc[g][b]);

        float tot[3][2];
        #pragma unroll
        for (int g = 0; g < 3; g++) {
            #pragma unroll
            for (int i = 0; i < 2; i++) {
                float keepv = half ? s[g][2 + i] : s[g][i];
                float sendv = half ? s[g][i] : s[g][2 + i];
                tot[g][i] = keepv + __shfl_xor_sync(0xFFFFFFFFu, sendv, 1);
            }
        }

        {
            float r0g = sigf(xr0 + tot[0][0]);
            float z0g = sigf(xz0 + tot[1][0]);
            float n0g = tanh_fast(fmaf(r0g, tot[2][0] + bn, xn0));
            float h0n = fmaf(z0g, hold[0] - n0g, n0g);
            hold[0] = h0n;
            hwr[(2 * half + 0) * HROW + hpos(j)] = h0n;

            float r1g = sigf(xr1 + tot[0][1]);
            float z1g = sigf(xz1 + tot[1][1]);
            float n1g = tanh_fast(fmaf(r1g, tot[2][1] + bn, xn1));
            float h1n = fmaf(z1g, hold[1] - n1g, n1g);
            hold[1] = h1n;
            hwr[(2 * half + 1) * HROW + hpos(j)] = h1n;
        }

        __syncthreads();
    }

    if (tid < 4 * 51) {
        const int b = tid / 51, o = tid % 51;
        float a = bfc[o];
        const float* wf = Wfc + o * 128;
        const float* hp = hs + b * HROW;
        #pragma unroll 8
        for (int k = 0; k < 128; k++) a = fmaf(hp[hpos(k)], wf[k], a);
        out[(b0 + b) * 51 + o] = a;
    }
}

// ---------------------------------------------------------------------------
// Launch
// ---------------------------------------------------------------------------
extern "C" void kernel_launch(void* const* d_in, const int* in_sizes, int n_in,
                              void* d_out, int out_size) {
    const float* x    = (const float*)d_in[0];  // [512,1,1024,64]
    const float* Wih  = (const float*)d_in[1];  // [384,64]
    const float* Whh  = (const float*)d_in[2];  // [384,128]
    const float* bih  = (const float*)d_in[3];  // [384]
    const float* bhh  = (const float*)d_in[4];  // [384]
    const float* Wfc  = (const float*)d_in[5];  // [51,128]
    const float* bfc  = (const float*)d_in[6];  // [51]
    float* out = (float*)d_out;                 // [512,51]

    wsplit<<<(G3 * In + 255) / 256, 256>>>(Wih);
    xg_gemm_tc<<<(Bn * Tn) / 128, 256>>>(x, bih, bhh);
    gru_kernel<<<128, 256>>>(Whh, bhh, Wfc, bfc, out);
}

// round 9
// speedup vs baseline: 1.5667x; 1.5175x over previous
#include <cuda_runtime.h>
#include <cstdint>
#include <cstddef>

#define Tn 1024
#define Bn 512
#define Hn 128
#define In 64
#define G3 384

// 805 MB scratch for precomputed input-side gate projections: xg[b][t][g]
__device__ float g_xg[(size_t)Bn * Tn * G3];

// ---------------------------------------------------------------------------
// Packed f32x2 FMA (Blackwell): d.lo += a.lo*b.lo ; d.hi += a.hi*b.hi
// ---------------------------------------------------------------------------
__device__ __forceinline__ void ffma2(unsigned long long& d,
                                      const unsigned long long a,
                                      const unsigned long long b) {
    asm("fma.rn.f32x2 %0, %1, %2, %0;" : "+l"(d) : "l"(a), "l"(b));
}

__device__ __forceinline__ float hsum2(unsigned long long v) {
    float lo, hi;
    asm("mov.b64 {%0, %1}, %2;" : "=f"(lo), "=f"(hi) : "l"(v));
    return lo + hi;
}

__device__ __forceinline__ float sigf(float x) {
    return __fdividef(1.0f, 1.0f + __expf(-x));
}
__device__ __forceinline__ float tanh_fast(float x) {
    return 1.0f - __fdividef(2.0f, 1.0f + __expf(2.0f * x));
}

// ---------------------------------------------------------------------------
// Kernel 1: xg[r][g] = x[r][:] . W_ih[g][:] + b_ih[g] + (g<256 ? b_hh[g] : 0)
// 64-row x 96-col tiles, 2 blocks/SM (R5 config — measured ~630us).
// Thread tile 4 rows x 6 cols, FFMA2, k-packed.
// ---------------------------------------------------------------------------
__global__ void __launch_bounds__(256, 2)
xg_gemm(const float* __restrict__ x,
        const float* __restrict__ Wih,
        const float* __restrict__ bih,
        const float* __restrict__ bhh) {
    __shared__ __align__(16) float xs[64 * 64];   // [row][k]
    __shared__ __align__(16) float ws[96 * 68];   // [col][k] padded

    const int tid = threadIdx.x;
    const int r0 = blockIdx.x * 64;
    const int cb = blockIdx.y;       // 0..3 -> 96 gate-cols each

    {
        const float4* xg4 = (const float4*)(x + (size_t)r0 * 64);
        float4* xs4 = (float4*)xs;
        #pragma unroll
        for (int i = tid; i < 64 * 16; i += 256) xs4[i] = xg4[i];
    }
    {
        const float4* wg4 = (const float4*)(Wih + (size_t)cb * 96 * 64);
        #pragma unroll
        for (int i = tid; i < 96 * 16; i += 256) {
            int g = i >> 4, k4 = i & 15;
            *(float4*)(ws + g * 68 + k4 * 4) = wg4[i];
        }
    }
    __syncthreads();

    const int ry = tid >> 4;   // 0..15 -> rows ry*4 .. +4
    const int cx = tid & 15;   // cols cx + 16*jj

    unsigned long long acc[4][6];
    #pragma unroll
    for (int i = 0; i < 4; i++)
        #pragma unroll
        for (int jj = 0; jj < 6; jj++) acc[i][jj] = 0ULL;

    #pragma unroll
    for (int k4 = 0; k4 < 16; k4++) {
        ulonglong2 wv[6];
        #pragma unroll
        for (int jj = 0; jj < 6; jj++)
            wv[jj] = *(const ulonglong2*)(ws + (cx + 16 * jj) * 68 + k4 * 4);
        #pragma unroll
        for (int i = 0; i < 4; i++) {
            ulonglong2 xv = *(const ulonglong2*)(xs + (ry * 4 + i) * 64 + k4 * 4);
            #pragma unroll
            for (int jj = 0; jj < 6; jj++) {
                ffma2(acc[i][jj], xv.x, wv[jj].x);
                ffma2(acc[i][jj], xv.y, wv[jj].y);
            }
        }
    }

    #pragma unroll
    for (int jj = 0; jj < 6; jj++) {
        const int g = cb * 96 + cx + 16 * jj;
        const float bias = bih[g] + (g < 256 ? bhh[g] : 0.0f);
        #pragma unroll
        for (int i = 0; i < 4; i++) {
            const int r = r0 + ry * 4 + i;
            g_xg[(size_t)r * G3 + g] = hsum2(acc[i][jj]) + bias;
        }
    }
}

// ---------------------------------------------------------------------------
// Kernel 2: GRU recurrence + final FC. (R4 config — proven 1732 us.)
// 128 blocks x 4 batches, 256 threads. Thread: j = tid>>1, half = tid&1.
// All 3 gate W row-halves in registers; h double-buffered; 1 barrier/step;
// cross-half reduction via shfl_xor(.,1).
// ---------------------------------------------------------------------------
#define HROW 136
__device__ __forceinline__ int hpos(int k) { return k + ((k >> 6) << 2); }

__global__ void __launch_bounds__(256, 1)
gru_kernel(const float* __restrict__ Whh,
           const float* __restrict__ bhh,
           const float* __restrict__ Wfc,
           const float* __restrict__ bfc,
           float* __restrict__ out) {
    __shared__ __align__(16) float hs[2 * 4 * HROW];

    const int tid = threadIdx.x;
    const int j = tid >> 1;
    const int half = tid & 1;
    const int b0 = blockIdx.x * 4;

    for (int i = tid; i < 4 * HROW; i += 256) hs[i] = 0.0f;

    ulonglong2 wrr[16], wzr[16], wnr[16];
    {
        const ulonglong2* wr_g = (const ulonglong2*)(Whh + (size_t)j * 128 + half * 64);
        const ulonglong2* wz_g = (const ulonglong2*)(Whh + (size_t)(j + 128) * 128 + half * 64);
        const ulonglong2* wn_g = (const ulonglong2*)(Whh + (size_t)(j + 256) * 128 + half * 64);
        #pragma unroll
        for (int kk = 0; kk < 16; kk++) {
            wrr[kk] = wr_g[kk];
            wzr[kk] = wz_g[kk];
            wnr[kk] = wn_g[kk];
        }
    }
    const float bn = bhh[256 + j];
    float hold[2] = {0.f, 0.f};

    const size_t xgA = ((size_t)(b0 + 2 * half) * Tn) * G3 + j;
    const size_t xgB = ((size_t)(b0 + 2 * half + 1) * Tn) * G3 + j;

    __syncthreads();

    for (int t = 0; t < Tn; t++) {
        const float* hrd = hs + (t & 1) * (4 * HROW);
        float* hwr = hs + ((t & 1) ^ 1) * (4 * HROW);

        const float* xpA = g_xg + xgA + (size_t)t * G3;
        const float* xpB = g_xg + xgB + (size_t)t * G3;
        float xr0 = xpA[0], xz0 = xpA[128], xn0 = xpA[256];
        float xr1 = xpB[0], xz1 = xpB[128], xn1 = xpB[256];

        unsigned long long acc[3][4];
        #pragma unroll
        for (int g = 0; g < 3; g++)
            #pragma unroll
            for (int b = 0; b < 4; b++) acc[g][b] = 0ULL;

        const float* hbase = hrd + half * 68;
        #pragma unroll
        for (int kk = 0; kk < 16; kk++) {
            const ulonglong2 wr = wrr[kk], wz = wzr[kk], wn = wnr[kk];
            #pragma unroll
            for (int b = 0; b < 4; b++) {
                ulonglong2 hv = *(const ulonglong2*)(hbase + b * HROW + kk * 4);
                ffma2(acc[0][b], wr.x, hv.x); ffma2(acc[0][b], wr.y, hv.y);
                ffma2(acc[1][b], wz.x, hv.x); ffma2(acc[1][b], wz.y, hv.y);
                ffma2(acc[2][b], wn.x, hv.x); ffma2(acc[2][b], wn.y, hv.y);
            }
        }

        float s[3][4];
        #pragma unroll
        for (int g = 0; g < 3; g++)
            #pragma unroll
            for (int b = 0; b < 4; b++) s[g][b] = hsum2(acc[g][b]);

        float tot[3][2];
        #pragma unroll
        for (int g = 0; g < 3; g++) {
            #pragma unroll
            for (int i = 0; i < 2; i++) {
                float keepv = half ? s[g][2 + i] : s[g][i];
                float sendv = half ? s[g][i] : s[g][2 + i];
                tot[g][i] = keepv + __shfl_xor_sync(0xFFFFFFFFu, sendv, 1);
            }
        }

        {
            float r0g = sigf(xr0 + tot[0][0]);
            float z0g = sigf(xz0 + tot[1][0]);
            float n0g = tanh_fast(fmaf(r0g, tot[2][0] + bn, xn0));
            float h0n = fmaf(z0g, hold[0] - n0g, n0g);
            hold[0] = h0n;
            hwr[(2 * half + 0) * HROW + hpos(j)] = h0n;

            float r1g = sigf(xr1 + tot[0][1]);
            float z1g = sigf(xz1 + tot[1][1]);
            float n1g = tanh_fast(fmaf(r1g, tot[2][1] + bn, xn1));
            float h1n = fmaf(z1g, hold[1] - n1g, n1g);
            hold[1] = h1n;
            hwr[(2 * half + 1) * HROW + hpos(j)] = h1n;
        }

        __syncthreads();
    }

    if (tid < 4 * 51) {
        const int b = tid / 51, o = tid % 51;
        float a = bfc[o];
        const float* wf = Wfc + o * 128;
        const float* hp = hs + b * HROW;
        #pragma unroll 8
        for (int k = 0; k < 128; k++) a = fmaf(hp[hpos(k)], wf[k], a);
        out[(b0 + b) * 51 + o] = a;
    }
}

// ---------------------------------------------------------------------------
// Launch
// ---------------------------------------------------------------------------
extern "C" void kernel_launch(void* const* d_in, const int* in_sizes, int n_in,
                              void* d_out, int out_size) {
    const float* x    = (const float*)d_in[0];  // [512,1,1024,64]
    const float* Wih  = (const float*)d_in[1];  // [384,64]
    const float* Whh  = (const float*)d_in[2];  // [384,128]
    const float* bih  = (const float*)d_in[3];  // [384]
    const float* bhh  = (const float*)d_in[4];  // [384]
    const float* Wfc  = (const float*)d_in[5];  // [51,128]
    const float* bfc  = (const float*)d_in[6];  // [51]
    float* out = (float*)d_out;                 // [512,51]

    xg_gemm<<<dim3((Bn * Tn) / 64, 4, 1), 256>>>(x, Wih, bih, bhh);
    gru_kernel<<<128, 256>>>(Whh, bhh, Wfc, bfc, out);
}